// round 2
// baseline (speedup 1.0000x reference)
#include <cuda_runtime.h>

#define NB   32
#define CIN  128
#define COUT 128
#define LEN  4096
#define KSZ  3
#define LT   128      // l-tile per CTA
#define IC   16       // i-chunk through smem

// Scratch (no allocations allowed): per-batch combined weights, layout [b][i][k][o]
__device__ float g_W2[NB * CIN * KSZ * COUT];     // 6.29 MB
__device__ float g_bias2[NB * COUT];

// ---------------------------------------------------------------------------
// Kernel 1: hypernetwork weight/bias materialization.
// combined_w[b,o,i,k] = weight[o,i,k]
//                     + sum_r (sum_c A[i,c,k]*codes[b,c,r]) * B[o,r,k]
// combined_b[b,o]     = bias[o] + sum_r codes[b,r,r] * bias_ctx[r,o]
// Stored as g_W2[b][i][k][o] so the conv kernel loads o-contiguous float4.
// ---------------------------------------------------------------------------
__global__ void geps_prep_kernel(const float* __restrict__ codes,
                                 const float* __restrict__ weight,
                                 const float* __restrict__ A,
                                 const float* __restrict__ Bm,
                                 const float* __restrict__ bias,
                                 const float* __restrict__ bctx) {
    const int b = blockIdx.x;
    const float c00 = codes[b * 4 + 0];  // codes[b][0][0]
    const float c01 = codes[b * 4 + 1];  // codes[b][0][1]
    const float c10 = codes[b * 4 + 2];  // codes[b][1][0]
    const float c11 = codes[b * 4 + 3];  // codes[b][1][1]

    const int per_blk = (COUT * CIN * KSZ) / gridDim.y;     // 6144 with gridDim.y=8
    const int e0 = blockIdx.y * per_blk;

    for (int e = e0 + threadIdx.x; e < e0 + per_blk; e += blockDim.x) {
        const int o   = e / (CIN * KSZ);
        const int rem = e % (CIN * KSZ);
        const int i   = rem / KSZ;
        const int k   = rem % KSZ;

        const float a0 = A[i * 2 * KSZ + k];            // A[i][0][k]
        const float a1 = A[i * 2 * KSZ + KSZ + k];      // A[i][1][k]
        const float g0 = a0 * c00 + a1 * c10;           // r = 0
        const float g1 = a0 * c01 + a1 * c11;           // r = 1

        const float cw = weight[e]
                       + g0 * Bm[o * 2 * KSZ + k]        // B[o][0][k]
                       + g1 * Bm[o * 2 * KSZ + KSZ + k]; // B[o][1][k]

        g_W2[((b * CIN + i) * KSZ + k) * COUT + o] = cw;
    }

    if (blockIdx.y == 0 && threadIdx.x < COUT) {
        const int o = threadIdx.x;
        g_bias2[b * COUT + o] = bias[o] + c00 * bctx[o] + c11 * bctx[COUT + o];
    }
}

// ---------------------------------------------------------------------------
// Kernel 2: per-batch circular conv1d as implicit GEMM.
// Grid (LEN/LT, NB), 256 threads. Thread = 8(o) x 8(l) register tile.
// ---------------------------------------------------------------------------
__global__ __launch_bounds__(256, 2)
void geps_conv_kernel(const float* __restrict__ x, float* __restrict__ out) {
    __shared__ float sw[IC * KSZ * COUT];   // 24 KB, layout [(i*K+k)][o]
    __shared__ float sx[IC][LT + 4];        // 16x132 floats

    const int b  = blockIdx.y;
    const int l0 = blockIdx.x * LT;
    const int tid = threadIdx.x;
    const int tx = tid & 15;                // l direction
    const int ty = tid >> 4;                // o direction
    const int o0 = ty * 8;
    const int lx = tx * 8;

    const float* xb = x + (size_t)b * CIN * LEN;
    const float* wb = g_W2 + (size_t)b * CIN * KSZ * COUT;

    float acc[8][8];
#pragma unroll
    for (int a = 0; a < 8; ++a)
#pragma unroll
        for (int c = 0; c < 8; ++c) acc[a][c] = 0.f;

    for (int i0 = 0; i0 < CIN; i0 += IC) {
        // weights: IC*KSZ*COUT = 6144 floats = 1536 float4 -> 6 per thread
        {
            const float4* wsrc = (const float4*)(wb + i0 * KSZ * COUT);
            float4* wdst = (float4*)sw;
#pragma unroll
            for (int t = 0; t < 6; ++t)
                wdst[tid + t * 256] = wsrc[tid + t * 256];
        }
        // input: IC rows x 130 cols, circular indexing at tile edges
        for (int e = tid; e < IC * 130; e += 256) {
            const int r  = e / 130;
            const int c  = e % 130;
            int gl = l0 - 1 + c;
            if (gl < 0) gl += LEN;
            else if (gl >= LEN) gl -= LEN;
            sx[r][c] = xb[(i0 + r) * LEN + gl];
        }
        __syncthreads();

#pragma unroll 2
        for (int i = 0; i < IC; ++i) {
            float xv[10];
#pragma unroll
            for (int j = 0; j < 10; ++j) xv[j] = sx[i][lx + j];
#pragma unroll
            for (int k = 0; k < KSZ; ++k) {
                const float* wrow = &sw[(i * KSZ + k) * COUT + o0];
                const float4 wa = *(const float4*)wrow;
                const float4 wc = *(const float4*)(wrow + 4);
                const float w[8] = {wa.x, wa.y, wa.z, wa.w, wc.x, wc.y, wc.z, wc.w};
#pragma unroll
                for (int oo = 0; oo < 8; ++oo)
#pragma unroll
                    for (int ll = 0; ll < 8; ++ll)
                        acc[oo][ll] += w[oo] * xv[ll + k];
            }
        }
        __syncthreads();
    }

    // epilogue: add bias, vectorized stores (8 consecutive l per o-row)
#pragma unroll
    for (int oo = 0; oo < 8; ++oo) {
        const int o = o0 + oo;
        const float bb = g_bias2[b * COUT + o];
        float* dst = out + ((size_t)(b * COUT + o)) * LEN + l0 + lx;
        float4 v0, v1;
        v0.x = acc[oo][0] + bb; v0.y = acc[oo][1] + bb;
        v0.z = acc[oo][2] + bb; v0.w = acc[oo][3] + bb;
        v1.x = acc[oo][4] + bb; v1.y = acc[oo][5] + bb;
        v1.z = acc[oo][6] + bb; v1.w = acc[oo][7] + bb;
        ((float4*)dst)[0] = v0;
        ((float4*)dst)[1] = v1;
    }
}

extern "C" void kernel_launch(void* const* d_in, const int* in_sizes, int n_in,
                              void* d_out, int out_size) {
    const float* input  = (const float*)d_in[0];   // (32,128,4096)
    const float* codes  = (const float*)d_in[1];   // (32,2,2)
    const float* weight = (const float*)d_in[2];   // (128,128,3)
    const float* A      = (const float*)d_in[3];   // (128,2,3)
    const float* Bm     = (const float*)d_in[4];   // (128,2,3)
    const float* bias   = (const float*)d_in[5];   // (128,)
    const float* bctx   = (const float*)d_in[6];   // (2,128)
    float* out = (float*)d_out;                    // (32,128,4096)

    dim3 pgrid(NB, 8);
    geps_prep_kernel<<<pgrid, 256>>>(codes, weight, A, Bm, bias, bctx);

    dim3 cgrid(LEN / LT, NB);
    geps_conv_kernel<<<cgrid, 256>>>(input, out);
}

// round 6
// speedup vs baseline: 1.2831x; 1.2831x over previous
#include <cuda_runtime.h>

#define NB   32
#define CIN  128
#define COUT 128
#define LEN  4096
#define KSZ  3
#define LT   128      // l-tile per CTA
#define IC   16       // i-chunk through smem
#define SXS  148      // swizzled x row stride (130 cols + c>>3 spread + pad)

typedef unsigned long long u64;

// Scratch: per-batch combined weights, layout [b][i][k][o] (o contiguous)
__device__ float g_W2[NB * CIN * KSZ * COUT];     // 6.29 MB
__device__ float g_bias2[NB * COUT];

__device__ __forceinline__ u64 dup2(float x) {
    u64 r; asm("mov.b64 %0, {%1, %1};" : "=l"(r) : "f"(x)); return r;
}
__device__ __forceinline__ u64 ffma2(u64 a, u64 b, u64 c) {
    u64 d; asm("fma.rn.f32x2 %0, %1, %2, %3;" : "=l"(d) : "l"(a), "l"(b), "l"(c)); return d;
}
__device__ __forceinline__ void unpack2(u64 v, float& lo, float& hi) {
    asm("mov.b64 {%0, %1}, %2;" : "=f"(lo), "=f"(hi) : "l"(v));
}

// ---------------------------------------------------------------------------
// Kernel 1: hypernetwork weight/bias materialization (unchanged math).
// ---------------------------------------------------------------------------
__global__ void geps_prep_kernel(const float* __restrict__ codes,
                                 const float* __restrict__ weight,
                                 const float* __restrict__ A,
                                 const float* __restrict__ Bm,
                                 const float* __restrict__ bias,
                                 const float* __restrict__ bctx) {
    const int b = blockIdx.x;
    const float c00 = codes[b * 4 + 0];
    const float c01 = codes[b * 4 + 1];
    const float c10 = codes[b * 4 + 2];
    const float c11 = codes[b * 4 + 3];

    const int per_blk = (COUT * CIN * KSZ) / gridDim.y;
    const int e0 = blockIdx.y * per_blk;

    for (int e = e0 + threadIdx.x; e < e0 + per_blk; e += blockDim.x) {
        const int o   = e / (CIN * KSZ);
        const int rem = e % (CIN * KSZ);
        const int i   = rem / KSZ;
        const int k   = rem % KSZ;

        const float a0 = A[i * 2 * KSZ + k];
        const float a1 = A[i * 2 * KSZ + KSZ + k];
        const float g0 = a0 * c00 + a1 * c10;
        const float g1 = a0 * c01 + a1 * c11;

        const float cw = weight[e]
                       + g0 * Bm[o * 2 * KSZ + k]
                       + g1 * Bm[o * 2 * KSZ + KSZ + k];

        g_W2[((b * CIN + i) * KSZ + k) * COUT + o] = cw;
    }

    if (blockIdx.y == 0 && threadIdx.x < COUT) {
        const int o = threadIdx.x;
        g_bias2[b * COUT + o] = bias[o] + c00 * bctx[o] + c11 * bctx[COUT + o];
    }
}

// ---------------------------------------------------------------------------
// Kernel 2: implicit-GEMM conv with packed f32x2 FMAs.
// Thread tile: 8(o) x 8(l); acc packed as 4 o-pairs x 8 l.
// ---------------------------------------------------------------------------
__global__ __launch_bounds__(256, 2)
void geps_conv_kernel(const float* __restrict__ x, float* __restrict__ out) {
    __shared__ __align__(16) float sw[IC * KSZ * COUT];   // 24 KB, [(i*K+k)][o]
    __shared__ __align__(16) float sxs[IC * SXS];         // swizzled x, 9.25 KB

    const int b  = blockIdx.y;
    const int l0 = blockIdx.x * LT;
    const int tid = threadIdx.x;
    const int tx = tid & 15;                // l direction
    const int ty = tid >> 4;                // o direction
    const int o0 = ty * 8;
    const int lx = tx * 8;

    const float* xb = x + (size_t)b * CIN * LEN;
    const float* wb = g_W2 + (size_t)b * CIN * KSZ * COUT;

    u64 acc[4][8];
#pragma unroll
    for (int p = 0; p < 4; ++p)
#pragma unroll
        for (int c = 0; c < 8; ++c) acc[p][c] = 0ull;

    for (int i0 = 0; i0 < CIN; i0 += IC) {
        // weights: IC*KSZ*COUT = 6144 floats = 1536 float4 -> 6 per thread
        {
            const float4* wsrc = (const float4*)(wb + i0 * KSZ * COUT);
            float4* wdst = (float4*)sw;
#pragma unroll
            for (int t = 0; t < 6; ++t)
                wdst[tid + t * 256] = wsrc[tid + t * 256];
        }
        // input: IC rows x 130 cols, circular at edges, swizzled column index
        for (int e = tid; e < IC * 130; e += 256) {
            const int r  = e / 130;
            const int c  = e % 130;
            int gl = l0 - 1 + c;
            if (gl < 0) gl += LEN;
            else if (gl >= LEN) gl -= LEN;
            sxs[r * SXS + c + (c >> 3)] = xb[(i0 + r) * LEN + gl];
        }
        __syncthreads();

#pragma unroll
        for (int i = 0; i < IC; ++i) {
            // duplicate x values into f32x2 pairs (conflict-free LDS via swizzle)
            u64 xd[10];
            const float* xrow = &sxs[i * SXS];
#pragma unroll
            for (int j = 0; j < 10; ++j) {
                const int c = lx + j;
                xd[j] = dup2(xrow[c + (c >> 3)]);
            }
#pragma unroll
            for (int k = 0; k < KSZ; ++k) {
                // 4 aligned o-pairs straight from smem (64-bit loads)
                const u64* wrow = (const u64*)&sw[(i * KSZ + k) * COUT + o0];
                u64 wp[4];
#pragma unroll
                for (int p = 0; p < 4; ++p) wp[p] = wrow[p];
#pragma unroll
                for (int p = 0; p < 4; ++p)
#pragma unroll
                    for (int ll = 0; ll < 8; ++ll)
                        acc[p][ll] = ffma2(wp[p], xd[ll + k], acc[p][ll]);
            }
        }
        __syncthreads();
    }

    // epilogue: unpack o-pairs, add bias, vectorized stores
#pragma unroll
    for (int p = 0; p < 4; ++p) {
        const int o_lo = o0 + 2 * p;
        const int o_hi = o_lo + 1;
        const float b_lo = g_bias2[b * COUT + o_lo];
        const float b_hi = g_bias2[b * COUT + o_hi];

        float rlo[8], rhi[8];
#pragma unroll
        for (int ll = 0; ll < 8; ++ll) {
            float lo, hi;
            unpack2(acc[p][ll], lo, hi);
            rlo[ll] = lo + b_lo;
            rhi[ll] = hi + b_hi;
        }
        float* dlo = out + ((size_t)(b * COUT + o_lo)) * LEN + l0 + lx;
        float* dhi = out + ((size_t)(b * COUT + o_hi)) * LEN + l0 + lx;
        ((float4*)dlo)[0] = make_float4(rlo[0], rlo[1], rlo[2], rlo[3]);
        ((float4*)dlo)[1] = make_float4(rlo[4], rlo[5], rlo[6], rlo[7]);
        ((float4*)dhi)[0] = make_float4(rhi[0], rhi[1], rhi[2], rhi[3]);
        ((float4*)dhi)[1] = make_float4(rhi[4], rhi[5], rhi[6], rhi[7]);
    }
}

extern "C" void kernel_launch(void* const* d_in, const int* in_sizes, int n_in,
                              void* d_out, int out_size) {
    const float* input  = (const float*)d_in[0];   // (32,128,4096)
    const float* codes  = (const float*)d_in[1];   // (32,2,2)
    const float* weight = (const float*)d_in[2];   // (128,128,3)
    const float* A      = (const float*)d_in[3];   // (128,2,3)
    const float* Bm     = (const float*)d_in[4];   // (128,2,3)
    const float* bias   = (const float*)d_in[5];   // (128,)
    const float* bctx   = (const float*)d_in[6];   // (2,128)
    float* out = (float*)d_out;                    // (32,128,4096)

    dim3 pgrid(NB, 8);
    geps_prep_kernel<<<pgrid, 256>>>(codes, weight, A, Bm, bias, bctx);

    dim3 cgrid(LEN / LT, NB);
    geps_conv_kernel<<<cgrid, 256>>>(input, out);
}

// round 7
// speedup vs baseline: 1.5062x; 1.1738x over previous
#include <cuda_runtime.h>
#include <cstdint>

#define NB   32
#define CIN  128
#define COUT 128
#define LEN  4096
#define KSZ  3
#define LT   128      // l-tile per CTA
#define IC   8        // i-chunk through smem (halved for double buffering)
#define SXS  148      // swizzled x row stride
#define NCHUNK (CIN / IC)   // 16

typedef unsigned long long u64;

// Scratch: per-batch combined weights, layout [b][i][k][o] (o contiguous)
__device__ float g_W2[NB * CIN * KSZ * COUT];     // 6.29 MB
__device__ float g_bias2[NB * COUT];

__device__ __forceinline__ u64 dup2(float x) {
    u64 r; asm("mov.b64 %0, {%1, %1};" : "=l"(r) : "f"(x)); return r;
}
__device__ __forceinline__ u64 ffma2(u64 a, u64 b, u64 c) {
    u64 d; asm("fma.rn.f32x2 %0, %1, %2, %3;" : "=l"(d) : "l"(a), "l"(b), "l"(c)); return d;
}
__device__ __forceinline__ void unpack2(u64 v, float& lo, float& hi) {
    asm("mov.b64 {%0, %1}, %2;" : "=f"(lo), "=f"(hi) : "l"(v));
}
__device__ __forceinline__ void cp16(uint32_t saddr, const float* g) {
    asm volatile("cp.async.cg.shared.global [%0], [%1], 16;\n" :: "r"(saddr), "l"(g));
}
#define CP_COMMIT() asm volatile("cp.async.commit_group;\n" ::: "memory")
#define CP_WAIT0()  asm volatile("cp.async.wait_group 0;\n" ::: "memory")

// ---------------------------------------------------------------------------
// Kernel 1: hypernetwork weight/bias materialization.
// ---------------------------------------------------------------------------
__global__ void geps_prep_kernel(const float* __restrict__ codes,
                                 const float* __restrict__ weight,
                                 const float* __restrict__ A,
                                 const float* __restrict__ Bm,
                                 const float* __restrict__ bias,
                                 const float* __restrict__ bctx) {
    const int b = blockIdx.x;
    const float c00 = codes[b * 4 + 0];
    const float c01 = codes[b * 4 + 1];
    const float c10 = codes[b * 4 + 2];
    const float c11 = codes[b * 4 + 3];

    const int per_blk = (COUT * CIN * KSZ) / gridDim.y;
    const int e0 = blockIdx.y * per_blk;

    for (int e = e0 + threadIdx.x; e < e0 + per_blk; e += blockDim.x) {
        const int o   = e / (CIN * KSZ);
        const int rem = e % (CIN * KSZ);
        const int i   = rem / KSZ;
        const int k   = rem % KSZ;

        const float a0 = A[i * 2 * KSZ + k];
        const float a1 = A[i * 2 * KSZ + KSZ + k];
        const float g0 = a0 * c00 + a1 * c10;
        const float g1 = a0 * c01 + a1 * c11;

        const float cw = weight[e]
                       + g0 * Bm[o * 2 * KSZ + k]
                       + g1 * Bm[o * 2 * KSZ + KSZ + k];

        g_W2[((b * CIN + i) * KSZ + k) * COUT + o] = cw;
    }

    if (blockIdx.y == 0 && threadIdx.x < COUT) {
        const int o = threadIdx.x;
        g_bias2[b * COUT + o] = bias[o] + c00 * bctx[o] + c11 * bctx[COUT + o];
    }
}

// ---------------------------------------------------------------------------
// Kernel 2: pipelined implicit-GEMM conv with packed f32x2 FMAs.
// Double-buffered smem: w via cp.async, x via LDG.128 register prefetch.
// ---------------------------------------------------------------------------
__global__ __launch_bounds__(256, 2)
void geps_conv_kernel(const float* __restrict__ x, float* __restrict__ out) {
    __shared__ __align__(16) float sw[2][IC * KSZ * COUT];   // 2 x 12 KB
    __shared__ __align__(16) float sxs[2][IC * SXS];         // 2 x 4.6 KB

    const int b  = blockIdx.y;
    const int l0 = blockIdx.x * LT;
    const int tid = threadIdx.x;
    const int tx = tid & 15;                // l direction
    const int ty = tid >> 4;                // o direction
    const int o0 = ty * 8;
    const int lx = tx * 8;

    const float* xb = x + (size_t)b * CIN * LEN;
    const float* wb = g_W2 + (size_t)b * CIN * KSZ * COUT;

    // ---- per-thread load mapping ----
    // x interior: row r = tid>>5 (0..7), t = tid&31, float4 at col c0 = 1+4t
    const int xr = tid >> 5;
    const int xt = tid & 31;
    const int xc0 = 1 + 4 * xt;
    // x halo: tid<16 -> row tid>>1, side tid&1 (c=0 left, c=129 right)
    const int hr = tid >> 1;
    const int hc = (tid & 1) ? 129 : 0;
    int hgl = (tid & 1) ? (l0 + 128) : (l0 - 1);
    if (hgl < 0) hgl += LEN;
    if (hgl >= LEN) hgl -= LEN;

    float4 xstage;          // interior prefetch
    float  hstage = 0.f;    // halo prefetch

    // w: IC*KSZ*COUT = 3072 floats = 768 float4 -> 3 per thread
    const uint32_t sw_base0 = (uint32_t)__cvta_generic_to_shared(&sw[0][0]);
    const uint32_t sw_base1 = (uint32_t)__cvta_generic_to_shared(&sw[1][0]);

    u64 acc[4][8];
#pragma unroll
    for (int p = 0; p < 4; ++p)
#pragma unroll
        for (int c = 0; c < 8; ++c) acc[p][c] = 0ull;

    // ---- prologue: start chunk 0 ----
    {
        const float* wsrc = wb;   // i0 = 0
#pragma unroll
        for (int t = 0; t < 3; ++t)
            cp16(sw_base0 + (tid + t * 256) * 16, wsrc + (tid + t * 256) * 4);
        CP_COMMIT();
        xstage = *(const float4*)(xb + xr * LEN + l0 + 4 * xt);
        if (tid < 16) hstage = xb[hr * LEN + hgl];
    }

    for (int cch = 0; cch < NCHUNK; ++cch) {
        const int buf = cch & 1;
        const int nbuf = buf ^ 1;

        // wait for this chunk's weights, scatter staged x into smem
        CP_WAIT0();
        {
            float* xrow = &sxs[buf][xr * SXS];
            const float xv[4] = {xstage.x, xstage.y, xstage.z, xstage.w};
#pragma unroll
            for (int j = 0; j < 4; ++j) {
                const int c = xc0 + j;
                xrow[c + (c >> 3)] = xv[j];
            }
            if (tid < 16)
                sxs[buf][hr * SXS + hc + (hc >> 3)] = hstage;
        }
        __syncthreads();

        // issue next chunk's loads (hidden under compute below)
        if (cch + 1 < NCHUNK) {
            const int i0n = (cch + 1) * IC;
            const float* wsrc = wb + i0n * KSZ * COUT;
            const uint32_t swb = nbuf ? sw_base1 : sw_base0;
#pragma unroll
            for (int t = 0; t < 3; ++t)
                cp16(swb + (tid + t * 256) * 16, wsrc + (tid + t * 256) * 4);
            CP_COMMIT();
            xstage = *(const float4*)(xb + (i0n + xr) * LEN + l0 + 4 * xt);
            if (tid < 16) hstage = xb[(i0n + hr) * LEN + hgl];
        }

        // ---- compute this chunk ----
        const float* swc = &sw[buf][0];
#pragma unroll
        for (int i = 0; i < IC; ++i) {
            const float* xrow = &sxs[buf][i * SXS + 9 * tx];
            u64 xd[10];
#pragma unroll
            for (int j = 0; j < 8; ++j) xd[j] = dup2(xrow[j]);
            xd[8] = dup2(xrow[9]);
            xd[9] = dup2(xrow[10]);
#pragma unroll
            for (int k = 0; k < KSZ; ++k) {
                const u64* wrow = (const u64*)&swc[(i * KSZ + k) * COUT + o0];
                u64 wp[4];
#pragma unroll
                for (int p = 0; p < 4; ++p) wp[p] = wrow[p];
#pragma unroll
                for (int p = 0; p < 4; ++p)
#pragma unroll
                    for (int ll = 0; ll < 8; ++ll)
                        acc[p][ll] = ffma2(wp[p], xd[ll + k], acc[p][ll]);
            }
        }
        __syncthreads();
    }

    // ---- epilogue ----
#pragma unroll
    for (int p = 0; p < 4; ++p) {
        const int o_lo = o0 + 2 * p;
        const int o_hi = o_lo + 1;
        const float b_lo = g_bias2[b * COUT + o_lo];
        const float b_hi = g_bias2[b * COUT + o_hi];

        float rlo[8], rhi[8];
#pragma unroll
        for (int ll = 0; ll < 8; ++ll) {
            float lo, hi;
            unpack2(acc[p][ll], lo, hi);
            rlo[ll] = lo + b_lo;
            rhi[ll] = hi + b_hi;
        }
        float* dlo = out + ((size_t)(b * COUT + o_lo)) * LEN + l0 + lx;
        float* dhi = out + ((size_t)(b * COUT + o_hi)) * LEN + l0 + lx;
        ((float4*)dlo)[0] = make_float4(rlo[0], rlo[1], rlo[2], rlo[3]);
        ((float4*)dlo)[1] = make_float4(rlo[4], rlo[5], rlo[6], rlo[7]);
        ((float4*)dhi)[0] = make_float4(rhi[0], rhi[1], rhi[2], rhi[3]);
        ((float4*)dhi)[1] = make_float4(rhi[4], rhi[5], rhi[6], rhi[7]);
    }
}

extern "C" void kernel_launch(void* const* d_in, const int* in_sizes, int n_in,
                              void* d_out, int out_size) {
    const float* input  = (const float*)d_in[0];   // (32,128,4096)
    const float* codes  = (const float*)d_in[1];   // (32,2,2)
    const float* weight = (const float*)d_in[2];   // (128,128,3)
    const float* A      = (const float*)d_in[3];   // (128,2,3)
    const float* Bm     = (const float*)d_in[4];   // (128,2,3)
    const float* bias   = (const float*)d_in[5];   // (128,)
    const float* bctx   = (const float*)d_in[6];   // (2,128)
    float* out = (float*)d_out;                    // (32,128,4096)

    dim3 pgrid(NB, 16);
    geps_prep_kernel<<<pgrid, 256>>>(codes, weight, A, Bm, bias, bctx);

    dim3 cgrid(LEN / LT, NB);
    geps_conv_kernel<<<cgrid, 256>>>(input, out);
}

// round 10
// speedup vs baseline: 2.2068x; 1.4652x over previous
#include <cuda_runtime.h>
#include <cuda_bf16.h>
#include <cstdint>

#define NB   32
#define CIN  128
#define COUT 128
#define LEN  4096
#define KSZ  3
#define LT   64                 // l-tile (M) per CTA
#define XROWS 66
#define XSTRIDE 136             // bf16 per X row = 272B (17 x 16B, ldsm conflict-free)
#define XSPLIT_BYTES (XROWS * XSTRIDE * 2)      // 17952
#define WIMG 8192               // bf16 per W image: 64 i-rows x 128 o
#define WOFFB(buf, split) (((buf) * 2 + (split)) * 16384)
#define XOFF 65536
#define SMEM_TOTAL (XOFF + 2 * XSPLIT_BYTES)    // 101440 bytes

// Prepped W images: [b][kk][ic][split] -> 64 x 128 bf16 linear (swizzle at cp.async)
__device__ __align__(16) __nv_bfloat16 g_Wimg[NB * KSZ * 2 * 2 * WIMG];   // 12.6 MB
__device__ float g_bias2[NB * COUT];

// ---------------------------------------------------------------------------
// helpers (all baseline PTX, compile for compute_103)
// ---------------------------------------------------------------------------
__device__ __forceinline__ uint32_t smem_u32(const void* p) {
    return (uint32_t)__cvta_generic_to_shared(p);
}
__device__ __forceinline__ void cp16(uint32_t saddr, const void* g) {
    asm volatile("cp.async.cg.shared.global [%0], [%1], 16;\n" :: "r"(saddr), "l"(g));
}
#define CP_COMMIT() asm volatile("cp.async.commit_group;\n" ::: "memory")
#define CP_WAIT0()  asm volatile("cp.async.wait_group 0;\n" ::: "memory")

__device__ __forceinline__ void ldsm4(uint32_t* d, uint32_t a) {
    asm volatile("ldmatrix.sync.aligned.m8n8.x4.shared.b16 {%0,%1,%2,%3}, [%4];"
                 : "=r"(d[0]), "=r"(d[1]), "=r"(d[2]), "=r"(d[3]) : "r"(a));
}
__device__ __forceinline__ void ldsm4t(uint32_t* d, uint32_t a) {
    asm volatile("ldmatrix.sync.aligned.m8n8.x4.trans.shared.b16 {%0,%1,%2,%3}, [%4];"
                 : "=r"(d[0]), "=r"(d[1]), "=r"(d[2]), "=r"(d[3]) : "r"(a));
}
__device__ __forceinline__ void mma16816(float* c, const uint32_t* a, const uint32_t* b) {
    asm volatile("mma.sync.aligned.m16n8k16.row.col.f32.bf16.bf16.f32 "
                 "{%0,%1,%2,%3}, {%4,%5,%6,%7}, {%8,%9}, {%0,%1,%2,%3};"
                 : "+f"(c[0]), "+f"(c[1]), "+f"(c[2]), "+f"(c[3])
                 : "r"(a[0]), "r"(a[1]), "r"(a[2]), "r"(a[3]), "r"(b[0]), "r"(b[1]));
}

// ---------------------------------------------------------------------------
// Kernel 1: hypernetwork weights -> bf16 hi/lo split W images, [i_local][o] linear.
// ---------------------------------------------------------------------------
__global__ void geps_prep_kernel(const float* __restrict__ codes,
                                 const float* __restrict__ weight,
                                 const float* __restrict__ A,
                                 const float* __restrict__ Bm,
                                 const float* __restrict__ bias,
                                 const float* __restrict__ bctx) {
    const int b = blockIdx.x;
    const float c00 = codes[b * 4 + 0];
    const float c01 = codes[b * 4 + 1];
    const float c10 = codes[b * 4 + 2];
    const float c11 = codes[b * 4 + 3];

#pragma unroll
    for (int t = 0; t < 8; ++t) {
        const int e = blockIdx.y * 2048 + t * 256 + threadIdx.x;  // 16384 (o,i)
        const int o = e & 127;
        const int i = e >> 7;
        const int ic = i >> 6;
        const int il = i & 63;

#pragma unroll
        for (int kk = 0; kk < KSZ; ++kk) {
            const float a0 = A[i * 6 + kk];
            const float a1 = A[i * 6 + 3 + kk];
            const float g0 = a0 * c00 + a1 * c10;
            const float g1 = a0 * c01 + a1 * c11;
            const float cw = weight[(o * 128 + i) * 3 + kk]
                           + g0 * Bm[o * 6 + kk]
                           + g1 * Bm[o * 6 + 3 + kk];
            const __nv_bfloat16 hi = __float2bfloat16(cw);
            const __nv_bfloat16 lo = __float2bfloat16(cw - __bfloat162float(hi));
            const int base = (((b * 3 + kk) * 2 + ic) * 2);
            g_Wimg[(size_t)(base + 0) * WIMG + il * 128 + o] = hi;
            g_Wimg[(size_t)(base + 1) * WIMG + il * 128 + o] = lo;
        }
    }

    if (blockIdx.y == 0 && threadIdx.x < COUT) {
        const int o = threadIdx.x;
        g_bias2[b * COUT + o] = bias[o] + c00 * bctx[o] + c11 * bctx[COUT + o];
    }
}

// ---------------------------------------------------------------------------
// Kernel 2: HMMA (mma.sync bf16) 3-pass split implicit-GEMM conv.
// Grid (64 l-tiles, 32 b), 256 threads = 8 warps (2m x 4n), warp tile 32x32.
// ---------------------------------------------------------------------------
__global__ __launch_bounds__(256, 2)
void geps_mma_kernel(const float* __restrict__ x, float* __restrict__ out) {
    extern __shared__ char smem[];
    const int tid = threadIdx.x;
    const int wid = tid >> 5;
    const int lane = tid & 31;
    const int b  = blockIdx.y;
    const int l0 = blockIdx.x * LT;
    const float* xb = x + (size_t)b * CIN * LEN;

    __nv_bfloat16* sXhi = (__nv_bfloat16*)(smem + XOFF);
    __nv_bfloat16* sXlo = (__nv_bfloat16*)(smem + XOFF + XSPLIT_BYTES);
    float* sC = (float*)(smem + XOFF);     // epilogue overlay (64 x 130 f32)
    const uint32_t sbase = smem_u32(smem);

    // ---- X fill: rows = l (66: halo + 64 + halo), cols = i; hi/lo bf16 split
    for (int e = tid; e < 2048; e += 256) {
        const int i = e >> 4;
        const int c = e & 15;
        const float4 f4 = *(const float4*)(xb + (size_t)i * LEN + l0 + 4 * c);
        const float v[4] = {f4.x, f4.y, f4.z, f4.w};
#pragma unroll
        for (int j = 0; j < 4; ++j) {
            const int row = 4 * c + 1 + j;
            const __nv_bfloat16 h = __float2bfloat16(v[j]);
            sXhi[row * XSTRIDE + i] = h;
            sXlo[row * XSTRIDE + i] = __float2bfloat16(v[j] - __bfloat162float(h));
        }
    }
    {   // halo: row 0 = l0-1 (wrap), row 65 = l0+64 (wrap)
        const int i = tid >> 1;
        const int side = tid & 1;
        const int gl = side ? ((l0 + LT) & (LEN - 1)) : ((l0 + LEN - 1) & (LEN - 1));
        const int row = side ? (LT + 1) : 0;
        const float v = xb[(size_t)i * LEN + gl];
        const __nv_bfloat16 h = __float2bfloat16(v);
        sXhi[row * XSTRIDE + i] = h;
        sXlo[row * XSTRIDE + i] = __float2bfloat16(v - __bfloat162float(h));
    }

    // ---- lane-derived ldmatrix address components
    const int g = lane >> 3, r = lane & 7;
    const int arow = ((g & 1) << 3) + r;   // +8 row for odd address-groups
    const int achk = g >> 1;               // k-chunk select (0/1)
    const int wm = wid & 1, wn = wid >> 1;
    const int m0 = 32 * wm, n0 = 32 * wn;

    float acc[2][4][4];
#pragma unroll
    for (int mt = 0; mt < 2; ++mt)
#pragma unroll
        for (int nt = 0; nt < 4; ++nt)
#pragma unroll
            for (int q = 0; q < 4; ++q) acc[mt][nt][q] = 0.f;

    // ---- W chunk loader: 2 splits x 16KB, XOR-swizzled 16B chunks
    auto issue_w = [&](int step, int buf) {
        const int kk = step % 3, ic = step / 3;
#pragma unroll
        for (int split = 0; split < 2; ++split) {
            const __nv_bfloat16* src =
                g_Wimg + (size_t)((((b * 3 + kk) * 2 + ic) * 2) + split) * WIMG;
            const uint32_t dbase = sbase + WOFFB(buf, split);
#pragma unroll
            for (int t = 0; t < 4; ++t) {
                const int v = tid + t * 256;
                const int row = v >> 4, c = v & 15;
                cp16(dbase + row * 256 + ((c ^ (row & 7)) << 4), src + v * 8);
            }
        }
        CP_COMMIT();
    };

    issue_w(0, 0);

    for (int step = 0; step < 6; ++step) {
        const int buf = step & 1;
        CP_WAIT0();
        __syncthreads();                    // W(step) visible; prev compute done
        if (step + 1 < 6) issue_w(step + 1, buf ^ 1);

        const int kk = step % 3;
        const int ic = step / 3;
        const uint32_t xhib = sbase + XOFF;
        const uint32_t xlob = xhib + XSPLIT_BYTES;
        const uint32_t whib = sbase + WOFFB(buf, 0);
        const uint32_t wlob = sbase + WOFFB(buf, 1);

#pragma unroll
        for (int ks = 0; ks < 4; ++ks) {
            uint32_t ah[2][4], al[2][4], bh[8], bl[8];
#pragma unroll
            for (int mt = 0; mt < 2; ++mt) {
                const uint32_t off =
                    (uint32_t)((kk + m0 + 16 * mt + arow) * 272 +
                               (8 * ic + 2 * ks + achk) * 16);
                ldsm4(ah[mt], xhib + off);
                ldsm4(al[mt], xlob + off);
            }
            const int rowB = 16 * ks + arow;
#pragma unroll
            for (int h = 0; h < 2; ++h) {
                const int cB = 4 * wn + 2 * h + achk;
                const uint32_t off =
                    (uint32_t)(rowB * 256 + ((cB ^ (rowB & 7)) << 4));
                ldsm4t(&bh[4 * h], whib + off);
                ldsm4t(&bl[4 * h], wlob + off);
            }
#pragma unroll
            for (int mt = 0; mt < 2; ++mt)
#pragma unroll
                for (int nt = 0; nt < 4; ++nt) {
                    mma16816(acc[mt][nt], ah[mt], &bh[2 * nt]);   // hi*hi
                    mma16816(acc[mt][nt], al[mt], &bh[2 * nt]);   // lo*hi
                    mma16816(acc[mt][nt], ah[mt], &bl[2 * nt]);   // hi*lo
                }
        }
    }

    // ---- epilogue: stage C[l][o] through smem, then coalesced global stores
    __syncthreads();
    {
        const int gr = lane >> 2, cid = lane & 3;
#pragma unroll
        for (int mt = 0; mt < 2; ++mt)
#pragma unroll
            for (int nt = 0; nt < 4; ++nt) {
                const int m = m0 + 16 * mt + gr;
                const int n = n0 + 8 * nt + 2 * cid;
                *(float2*)&sC[m * 130 + n] =
                    make_float2(acc[mt][nt][0], acc[mt][nt][1]);
                *(float2*)&sC[(m + 8) * 130 + n] =
                    make_float2(acc[mt][nt][2], acc[mt][nt][3]);
            }
    }
    __syncthreads();
    {
        const float* bb = g_bias2 + b * COUT;
#pragma unroll
        for (int jj = 0; jj < 16; ++jj) {
            const int o = wid * 16 + jj;
            const float bv = bb[o];
            float* op = out + ((size_t)b * COUT + o) * LEN + l0;
#pragma unroll
            for (int half = 0; half < 2; ++half) {
                const int l = 32 * half + lane;
                op[l] = sC[l * 130 + o] + bv;
            }
        }
    }
}

extern "C" void kernel_launch(void* const* d_in, const int* in_sizes, int n_in,
                              void* d_out, int out_size) {
    const float* input  = (const float*)d_in[0];   // (32,128,4096)
    const float* codes  = (const float*)d_in[1];   // (32,2,2)
    const float* weight = (const float*)d_in[2];   // (128,128,3)
    const float* A      = (const float*)d_in[3];   // (128,2,3)
    const float* Bm     = (const float*)d_in[4];   // (128,2,3)
    const float* bias   = (const float*)d_in[5];   // (128,)
    const float* bctx   = (const float*)d_in[6];   // (2,128)
    float* out = (float*)d_out;                    // (32,128,4096)

    cudaFuncSetAttribute(geps_mma_kernel,
                         cudaFuncAttributeMaxDynamicSharedMemorySize, SMEM_TOTAL);

    dim3 pgrid(NB, 8);
    geps_prep_kernel<<<pgrid, 256>>>(codes, weight, A, Bm, bias, bctx);

    dim3 cgrid(LEN / LT, NB);
    geps_mma_kernel<<<cgrid, 256, SMEM_TOTAL>>>(input, out);
}

// round 11
// speedup vs baseline: 2.9779x; 1.3494x over previous
#include <cuda_runtime.h>
#include <cuda_fp16.h>
#include <cstdint>

#define NB   32
#define CIN  128
#define COUT 128
#define LEN  4096
#define KSZ  3
#define LT   64                 // l-tile (M) per CTA
#define XROWS 66
#define XSTRIDE 136             // fp16 per X row = 272B (17 x 16B, ldsm conflict-free)
#define XSPLIT_BYTES (XROWS * XSTRIDE * 2)      // 17952
#define WIMG 8192               // fp16 per W image: 64 i-rows x 128 o
#define WOFFB(buf) ((buf) * 16384)
#define XOFF 32768
#define SMEM_TOTAL (XOFF + 2 * XSPLIT_BYTES)    // 68672 bytes

// Prepped W images: [b][kk][ic] -> 64 x 128 fp16 linear (swizzle applied at cp.async)
__device__ __align__(16) __half g_Wimg[NB * KSZ * 2 * WIMG];   // 3.1 MB
__device__ float g_bias2[NB * COUT];

// ---------------------------------------------------------------------------
// helpers (baseline PTX, compiles for compute_103)
// ---------------------------------------------------------------------------
__device__ __forceinline__ uint32_t smem_u32(const void* p) {
    return (uint32_t)__cvta_generic_to_shared(p);
}
__device__ __forceinline__ void cp16(uint32_t saddr, const void* g) {
    asm volatile("cp.async.cg.shared.global [%0], [%1], 16;\n" :: "r"(saddr), "l"(g));
}
#define CP_COMMIT() asm volatile("cp.async.commit_group;\n" ::: "memory")
#define CP_WAIT0()  asm volatile("cp.async.wait_group 0;\n" ::: "memory")

__device__ __forceinline__ void ldsm4(uint32_t* d, uint32_t a) {
    asm volatile("ldmatrix.sync.aligned.m8n8.x4.shared.b16 {%0,%1,%2,%3}, [%4];"
                 : "=r"(d[0]), "=r"(d[1]), "=r"(d[2]), "=r"(d[3]) : "r"(a));
}
__device__ __forceinline__ void ldsm4t(uint32_t* d, uint32_t a) {
    asm volatile("ldmatrix.sync.aligned.m8n8.x4.trans.shared.b16 {%0,%1,%2,%3}, [%4];"
                 : "=r"(d[0]), "=r"(d[1]), "=r"(d[2]), "=r"(d[3]) : "r"(a));
}
__device__ __forceinline__ void mma16816(float* c, const uint32_t* a, const uint32_t* b) {
    asm volatile("mma.sync.aligned.m16n8k16.row.col.f32.f16.f16.f32 "
                 "{%0,%1,%2,%3}, {%4,%5,%6,%7}, {%8,%9}, {%0,%1,%2,%3};"
                 : "+f"(c[0]), "+f"(c[1]), "+f"(c[2]), "+f"(c[3])
                 : "r"(a[0]), "r"(a[1]), "r"(a[2]), "r"(a[3]), "r"(b[0]), "r"(b[1]));
}

// ---------------------------------------------------------------------------
// Kernel 1: hypernetwork weights -> single fp16 W images, [i_local][o] linear.
// ---------------------------------------------------------------------------
__global__ void geps_prep_kernel(const float* __restrict__ codes,
                                 const float* __restrict__ weight,
                                 const float* __restrict__ A,
                                 const float* __restrict__ Bm,
                                 const float* __restrict__ bias,
                                 const float* __restrict__ bctx) {
    const int b = blockIdx.x;
    const float c00 = codes[b * 4 + 0];
    const float c01 = codes[b * 4 + 1];
    const float c10 = codes[b * 4 + 2];
    const float c11 = codes[b * 4 + 3];

#pragma unroll
    for (int t = 0; t < 8; ++t) {
        const int e = blockIdx.y * 2048 + t * 256 + threadIdx.x;  // 16384 (o,i)
        const int o = e & 127;
        const int i = e >> 7;
        const int ic = i >> 6;
        const int il = i & 63;

#pragma unroll
        for (int kk = 0; kk < KSZ; ++kk) {
            const float a0 = A[i * 6 + kk];
            const float a1 = A[i * 6 + 3 + kk];
            const float g0 = a0 * c00 + a1 * c10;
            const float g1 = a0 * c01 + a1 * c11;
            const float cw = weight[(o * 128 + i) * 3 + kk]
                           + g0 * Bm[o * 6 + kk]
                           + g1 * Bm[o * 6 + 3 + kk];
            g_Wimg[(size_t)((b * 3 + kk) * 2 + ic) * WIMG + il * 128 + o] =
                __float2half(cw);
        }
    }

    if (blockIdx.y == 0 && threadIdx.x < COUT) {
        const int o = threadIdx.x;
        g_bias2[b * COUT + o] = bias[o] + c00 * bctx[o] + c11 * bctx[COUT + o];
    }
}

// ---------------------------------------------------------------------------
// Kernel 2: HMMA fp16 2-pass split (x = hi+lo fp16, W single fp16).
// Grid (64 l-tiles, 32 b), 256 threads = 8 warps (2m x 4n), warp tile 32x32.
// ---------------------------------------------------------------------------
__global__ __launch_bounds__(256, 2)
void geps_mma_kernel(const float* __restrict__ x, float* __restrict__ out) {
    extern __shared__ char smem[];
    const int tid = threadIdx.x;
    const int wid = tid >> 5;
    const int lane = tid & 31;
    const int b  = blockIdx.y;
    const int l0 = blockIdx.x * LT;
    const float* xb = x + (size_t)b * CIN * LEN;

    __half* sXhi = (__half*)(smem + XOFF);
    __half* sXlo = (__half*)(smem + XOFF + XSPLIT_BYTES);
    float* sC = (float*)(smem + XOFF);     // epilogue overlay (64 x 130 f32)
    const uint32_t sbase = smem_u32(smem);

    // ---- X fill: rows = l (66: halo + 64 + halo), cols = i; hi/lo fp16 split
    for (int e = tid; e < 2048; e += 256) {
        const int i = e >> 4;
        const int c = e & 15;
        const float4 f4 = *(const float4*)(xb + (size_t)i * LEN + l0 + 4 * c);
        const float v[4] = {f4.x, f4.y, f4.z, f4.w};
#pragma unroll
        for (int j = 0; j < 4; ++j) {
            const int row = 4 * c + 1 + j;
            const __half h = __float2half(v[j]);
            sXhi[row * XSTRIDE + i] = h;
            sXlo[row * XSTRIDE + i] = __float2half(v[j] - __half2float(h));
        }
    }
    {   // halo: row 0 = l0-1 (wrap), row 65 = l0+64 (wrap)
        const int i = tid >> 1;
        const int side = tid & 1;
        const int gl = side ? ((l0 + LT) & (LEN - 1)) : ((l0 + LEN - 1) & (LEN - 1));
        const int row = side ? (LT + 1) : 0;
        const float v = xb[(size_t)i * LEN + gl];
        const __half h = __float2half(v);
        sXhi[row * XSTRIDE + i] = h;
        sXlo[row * XSTRIDE + i] = __float2half(v - __half2float(h));
    }

    // ---- lane-derived ldmatrix address components
    const int g = lane >> 3, r = lane & 7;
    const int arow = ((g & 1) << 3) + r;   // +8 row for odd address-groups
    const int achk = g >> 1;               // k-chunk select (0/1)
    const int wm = wid & 1, wn = wid >> 1;
    const int m0 = 32 * wm, n0 = 32 * wn;

    float acc[2][4][4];
#pragma unroll
    for (int mt = 0; mt < 2; ++mt)
#pragma unroll
        for (int nt = 0; nt < 4; ++nt)
#pragma unroll
            for (int q = 0; q < 4; ++q) acc[mt][nt][q] = 0.f;

    // ---- W chunk loader: 16KB, XOR-swizzled 16B chunks
    auto issue_w = [&](int step, int buf) {
        const int kk = step % 3, ic = step / 3;
        const __half* src = (const __half*)g_Wimg
                          + (size_t)((b * 3 + kk) * 2 + ic) * WIMG;
        const uint32_t dbase = sbase + WOFFB(buf);
#pragma unroll
        for (int t = 0; t < 4; ++t) {
            const int v = tid + t * 256;
            const int row = v >> 4, c = v & 15;
            cp16(dbase + row * 256 + ((c ^ (row & 7)) << 4), src + v * 8);
        }
        CP_COMMIT();
    };

    issue_w(0, 0);

    for (int step = 0; step < 6; ++step) {
        const int buf = step & 1;
        CP_WAIT0();
        __syncthreads();                    // W(step) visible; prev compute done
        if (step + 1 < 6) issue_w(step + 1, buf ^ 1);

        const int kk = step % 3;
        const int ic = step / 3;
        const uint32_t xhib = sbase + XOFF;
        const uint32_t xlob = xhib + XSPLIT_BYTES;
        const uint32_t wb_ = sbase + WOFFB(buf);

#pragma unroll
        for (int ks = 0; ks < 4; ++ks) {
            uint32_t ah[2][4], al[2][4], bw[8];
#pragma unroll
            for (int mt = 0; mt < 2; ++mt) {
                const uint32_t off =
                    (uint32_t)((kk + m0 + 16 * mt + arow) * 272 +
                               (8 * ic + 2 * ks + achk) * 16);
                ldsm4(ah[mt], xhib + off);
                ldsm4(al[mt], xlob + off);
            }
            const int rowB = 16 * ks + arow;
#pragma unroll
            for (int h = 0; h < 2; ++h) {
                const int cB = 4 * wn + 2 * h + achk;
                const uint32_t off =
                    (uint32_t)(rowB * 256 + ((cB ^ (rowB & 7)) << 4));
                ldsm4t(&bw[4 * h], wb_ + off);
            }
#pragma unroll
            for (int mt = 0; mt < 2; ++mt)
#pragma unroll
                for (int nt = 0; nt < 4; ++nt) {
                    mma16816(acc[mt][nt], ah[mt], &bw[2 * nt]);   // hi pass
                    mma16816(acc[mt][nt], al[mt], &bw[2 * nt]);   // lo pass
                }
        }
    }

    // ---- epilogue: stage C[l][o] through smem, then coalesced global stores
    __syncthreads();
    {
        const int gr = lane >> 2, cid = lane & 3;
#pragma unroll
        for (int mt = 0; mt < 2; ++mt)
#pragma unroll
            for (int nt = 0; nt < 4; ++nt) {
                const int m = m0 + 16 * mt + gr;
                const int n = n0 + 8 * nt + 2 * cid;
                *(float2*)&sC[m * 130 + n] =
                    make_float2(acc[mt][nt][0], acc[mt][nt][1]);
                *(float2*)&sC[(m + 8) * 130 + n] =
                    make_float2(acc[mt][nt][2], acc[mt][nt][3]);
            }
    }
    __syncthreads();
    {
        const float* bb = g_bias2 + b * COUT;
#pragma unroll
        for (int jj = 0; jj < 16; ++jj) {
            const int o = wid * 16 + jj;
            const float bv = bb[o];
            float* op = out + ((size_t)b * COUT + o) * LEN + l0;
#pragma unroll
            for (int half = 0; half < 2; ++half) {
                const int l = 32 * half + lane;
                op[l] = sC[l * 130 + o] + bv;
            }
        }
    }
}

extern "C" void kernel_launch(void* const* d_in, const int* in_sizes, int n_in,
                              void* d_out, int out_size) {
    const float* input  = (const float*)d_in[0];   // (32,128,4096)
    const float* codes  = (const float*)d_in[1];   // (32,2,2)
    const float* weight = (const float*)d_in[2];   // (128,128,3)
    const float* A      = (const float*)d_in[3];   // (128,2,3)
    const float* Bm     = (const float*)d_in[4];   // (128,2,3)
    const float* bias   = (const float*)d_in[5];   // (128,)
    const float* bctx   = (const float*)d_in[6];   // (2,128)
    float* out = (float*)d_out;                    // (32,128,4096)

    cudaFuncSetAttribute(geps_mma_kernel,
                         cudaFuncAttributeMaxDynamicSharedMemorySize, SMEM_TOTAL);

    dim3 pgrid(NB, 8);
    geps_prep_kernel<<<pgrid, 256>>>(codes, weight, A, Bm, bias, bctx);

    dim3 cgrid(LEN / LT, NB);
    geps_mma_kernel<<<cgrid, 256, SMEM_TOTAL>>>(input, out);
}

// round 12
// speedup vs baseline: 4.7401x; 1.5918x over previous
#include <cuda_runtime.h>
#include <cuda_fp16.h>
#include <cstdint>

#define NB   32
#define CIN  128
#define COUT 128
#define LEN  4096
#define KSZ  3
#define LT   64                 // l-tile (M) per CTA
#define XSTRIDE 136             // fp16 per X row = 272B (ldsm-friendly)
#define STW 66                  // f32 staging row stride (words)
#define WOFFB(buf) ((buf) * 16384)
#define STOFF 32768             // f32 staging tile [128][STW] / epilogue sC overlay
#define XOFF  66560             // X fp16 tile [66][XSTRIDE]
#define SMEM_TOTAL (XOFF + 66 * XSTRIDE * 2)    // 84512 bytes

// Prepped W images: [b][kk][ic] -> 64 x 128 fp16 linear (swizzle applied at cp.async)
__device__ __align__(16) __half g_Wimg[NB * KSZ * 2 * 8192];   // 3.1 MB
__device__ float g_bias2[NB * COUT];

// ---------------------------------------------------------------------------
// helpers (baseline PTX, compiles for compute_103)
// ---------------------------------------------------------------------------
__device__ __forceinline__ uint32_t smem_u32(const void* p) {
    return (uint32_t)__cvta_generic_to_shared(p);
}
__device__ __forceinline__ void cp16(uint32_t saddr, const void* g) {
    asm volatile("cp.async.cg.shared.global [%0], [%1], 16;\n" :: "r"(saddr), "l"(g));
}
#define CP_COMMIT() asm volatile("cp.async.commit_group;\n" ::: "memory")
#define CP_WAIT0()  asm volatile("cp.async.wait_group 0;\n" ::: "memory")

__device__ __forceinline__ void ldsm4(uint32_t* d, uint32_t a) {
    asm volatile("ldmatrix.sync.aligned.m8n8.x4.shared.b16 {%0,%1,%2,%3}, [%4];"
                 : "=r"(d[0]), "=r"(d[1]), "=r"(d[2]), "=r"(d[3]) : "r"(a));
}
__device__ __forceinline__ void ldsm4t(uint32_t* d, uint32_t a) {
    asm volatile("ldmatrix.sync.aligned.m8n8.x4.trans.shared.b16 {%0,%1,%2,%3}, [%4];"
                 : "=r"(d[0]), "=r"(d[1]), "=r"(d[2]), "=r"(d[3]) : "r"(a));
}
__device__ __forceinline__ void mma16816(float* c, const uint32_t* a, const uint32_t* b) {
    asm volatile("mma.sync.aligned.m16n8k16.row.col.f32.f16.f16.f32 "
                 "{%0,%1,%2,%3}, {%4,%5,%6,%7}, {%8,%9}, {%0,%1,%2,%3};"
                 : "+f"(c[0]), "+f"(c[1]), "+f"(c[2]), "+f"(c[3])
                 : "r"(a[0]), "r"(a[1]), "r"(a[2]), "r"(a[3]), "r"(b[0]), "r"(b[1]));
}

// ---------------------------------------------------------------------------
// Kernel 1: hypernetwork weights -> single fp16 W images, [i_local][o] linear.
// ---------------------------------------------------------------------------
__global__ void geps_prep_kernel(const float* __restrict__ codes,
                                 const float* __restrict__ weight,
                                 const float* __restrict__ A,
                                 const float* __restrict__ Bm,
                                 const float* __restrict__ bias,
                                 const float* __restrict__ bctx) {
    const int b = blockIdx.x;
    const float c00 = codes[b * 4 + 0];
    const float c01 = codes[b * 4 + 1];
    const float c10 = codes[b * 4 + 2];
    const float c11 = codes[b * 4 + 3];

#pragma unroll
    for (int t = 0; t < 8; ++t) {
        const int e = blockIdx.y * 2048 + t * 256 + threadIdx.x;  // 16384 (o,i)
        const int o = e & 127;
        const int i = e >> 7;
        const int ic = i >> 6;
        const int il = i & 63;

#pragma unroll
        for (int kk = 0; kk < KSZ; ++kk) {
            const float a0 = A[i * 6 + kk];
            const float a1 = A[i * 6 + 3 + kk];
            const float g0 = a0 * c00 + a1 * c10;
            const float g1 = a0 * c01 + a1 * c11;
            const float cw = weight[(o * 128 + i) * 3 + kk]
                           + g0 * Bm[o * 6 + kk]
                           + g1 * Bm[o * 6 + 3 + kk];
            g_Wimg[(size_t)((b * 3 + kk) * 2 + ic) * 8192 + il * 128 + o] =
                __float2half(cw);
        }
    }

    if (blockIdx.y == 0 && threadIdx.x < COUT) {
        const int o = threadIdx.x;
        g_bias2[b * COUT + o] = bias[o] + c00 * bctx[o] + c11 * bctx[COUT + o];
    }
}

// ---------------------------------------------------------------------------
// Kernel 2: HMMA fp16 single-pass implicit-GEMM conv, conflict-free smem paths.
// Grid (64 l-tiles, 32 b), 256 threads = 8 warps (2m x 4n), warp tile 32x32.
// ---------------------------------------------------------------------------
__global__ __launch_bounds__(256, 2)
void geps_mma_kernel(const float* __restrict__ x, float* __restrict__ out) {
    extern __shared__ char smem[];
    const int tid = threadIdx.x;
    const int wid = tid >> 5;
    const int lane = tid & 31;
    const int b  = blockIdx.y;
    const int l0 = blockIdx.x * LT;
    const float* xb = x + (size_t)b * CIN * LEN;

    float*  sT  = (float*)(smem + STOFF);            // staging [128][STW] f32
    float*  sC  = (float*)(smem + STOFF);            // epilogue overlay
    __half* sXh = (__half*)(smem + XOFF);            // [66][XSTRIDE] fp16
    const uint32_t sbase = smem_u32(smem);

    // ---- W chunk loader: 16KB, XOR-swizzled 16B chunks
    auto issue_w = [&](int step, int buf) {
        const int kk = step % 3, ic = step / 3;
        const __half* src = (const __half*)g_Wimg
                          + (size_t)((b * 3 + kk) * 2 + ic) * 8192;
        const uint32_t dbase = sbase + WOFFB(buf);
#pragma unroll
        for (int t = 0; t < 4; ++t) {
            const int v = tid + t * 256;
            const int row = v >> 4, c = v & 15;
            cp16(dbase + row * 256 + ((c ^ (row & 7)) << 4), src + v * 8);
        }
        CP_COMMIT();
    };

    issue_w(0, 0);    // overlap W0 with X fill

    // ---- X fill stage A: coalesced copy x[i][l0..l0+63] -> sT[i][l'] (f32)
    {
        const int lane_c = tid & 7;
        const int lane_i = (tid >> 3) & 3;
        const int wq = tid >> 5;
#pragma unroll
        for (int t = 0; t < 8; ++t) {
            const int combo = wq + 8 * t;              // 0..63
            const int i = lane_i + 4 * (combo & 31);
            const int c = lane_c + 8 * (combo >> 5);   // 0..15
            const float4 v = *(const float4*)(xb + (size_t)i * LEN + l0 + 4 * c);
            float* dst = sT + i * STW + 4 * c;
            *(float2*)(dst)     = make_float2(v.x, v.y);
            *(float2*)(dst + 2) = make_float2(v.z, v.w);
        }
    }
    // halo rows: row 0 = l0-1 (wrap), row 65 = l0+64 (wrap), direct to sXh
    {
        const int i = tid & 127;
        const int side = tid >> 7;
        const int gl = side ? ((l0 + LT) & (LEN - 1)) : ((l0 + LEN - 1) & (LEN - 1));
        const int row = side ? (LT + 1) : 0;
        sXh[row * XSTRIDE + i] = __float2half(xb[(size_t)i * LEN + gl]);
    }
    __syncthreads();

    // ---- X fill stage B: transpose sT -> sXh[l+1][i], conflict-free LDS.32
    {
        const int rB  = tid & 63;      // l offset 0..63
        const int ibB = tid >> 6;      // 0..3
#pragma unroll
        for (int t = 0; t < 8; ++t) {
            const int ib = ibB + 4 * t;               // 0..31, i = 4*ib..+3
            const float a0 = sT[(4 * ib + 0) * STW + rB];
            const float a1 = sT[(4 * ib + 1) * STW + rB];
            const float a2 = sT[(4 * ib + 2) * STW + rB];
            const float a3 = sT[(4 * ib + 3) * STW + rB];
            __half2 h01 = __floats2half2_rn(a0, a1);
            __half2 h23 = __floats2half2_rn(a2, a3);
            union { uint2 u; __half2 h[2]; } pk;
            pk.h[0] = h01; pk.h[1] = h23;
            *(uint2*)(&sXh[(rB + 1) * XSTRIDE + 4 * ib]) = pk.u;
        }
    }

    // ---- lane-derived ldmatrix address components
    const int g = lane >> 3, r = lane & 7;
    const int arow = ((g & 1) << 3) + r;
    const int achk = g >> 1;
    const int wm = wid & 1, wn = wid >> 1;
    const int m0 = 32 * wm, n0 = 32 * wn;

    float acc[2][4][4];
#pragma unroll
    for (int mt = 0; mt < 2; ++mt)
#pragma unroll
        for (int nt = 0; nt < 4; ++nt)
#pragma unroll
            for (int q = 0; q < 4; ++q) acc[mt][nt][q] = 0.f;

    const uint32_t xhib = sbase + XOFF;

    for (int step = 0; step < 6; ++step) {
        const int buf = step & 1;
        CP_WAIT0();
        __syncthreads();                 // W(step) + stage-B X visible
        if (step + 1 < 6) issue_w(step + 1, buf ^ 1);

        const int kk = step % 3;
        const int ic = step / 3;
        const uint32_t wb_ = sbase + WOFFB(buf);

#pragma unroll
        for (int ks = 0; ks < 4; ++ks) {
            uint32_t ah[2][4], bw[8];
#pragma unroll
            for (int mt = 0; mt < 2; ++mt) {
                const uint32_t off =
                    (uint32_t)((kk + m0 + 16 * mt + arow) * 272 +
                               (8 * ic + 2 * ks + achk) * 16);
                ldsm4(ah[mt], xhib + off);
            }
            const int rowB = 16 * ks + arow;
#pragma unroll
            for (int h = 0; h < 2; ++h) {
                const int cB = 4 * wn + 2 * h + achk;
                const uint32_t off =
                    (uint32_t)(rowB * 256 + ((cB ^ (rowB & 7)) << 4));
                ldsm4t(&bw[4 * h], wb_ + off);
            }
#pragma unroll
            for (int mt = 0; mt < 2; ++mt)
#pragma unroll
                for (int nt = 0; nt < 4; ++nt)
                    mma16816(acc[mt][nt], ah[mt], &bw[2 * nt]);
        }
    }

    // ---- epilogue: stage C[l][o] through smem (stride 131), coalesced stores
    __syncthreads();
    {
        const int gr = lane >> 2, cid = lane & 3;
#pragma unroll
        for (int mt = 0; mt < 2; ++mt)
#pragma unroll
            for (int nt = 0; nt < 4; ++nt) {
                const int m = m0 + 16 * mt + gr;
                const int n = n0 + 8 * nt + 2 * cid;
                sC[m * 131 + n]           = acc[mt][nt][0];
                sC[m * 131 + n + 1]       = acc[mt][nt][1];
                sC[(m + 8) * 131 + n]     = acc[mt][nt][2];
                sC[(m + 8) * 131 + n + 1] = acc[mt][nt][3];
            }
    }
    __syncthreads();
    {
        const float* bb = g_bias2 + b * COUT;
#pragma unroll
        for (int jj = 0; jj < 16; ++jj) {
            const int o = wid * 16 + jj;
            const float bv = bb[o];
            float* op = out + ((size_t)b * COUT + o) * LEN + l0;
#pragma unroll
            for (int half = 0; half < 2; ++half) {
                const int l = 32 * half + lane;
                op[l] = sC[l * 131 + o] + bv;
            }
        }
    }
}

extern "C" void kernel_launch(void* const* d_in, const int* in_sizes, int n_in,
                              void* d_out, int out_size) {
    const float* input  = (const float*)d_in[0];   // (32,128,4096)
    const float* codes  = (const float*)d_in[1];   // (32,2,2)
    const float* weight = (const float*)d_in[2];   // (128,128,3)
    const float* A      = (const float*)d_in[3];   // (128,2,3)
    const float* Bm     = (const float*)d_in[4];   // (128,2,3)
    const float* bias   = (const float*)d_in[5];   // (128,)
    const float* bctx   = (const float*)d_in[6];   // (2,128)
    float* out = (float*)d_out;                    // (32,128,4096)

    cudaFuncSetAttribute(geps_mma_kernel,
                         cudaFuncAttributeMaxDynamicSharedMemorySize, SMEM_TOTAL);

    dim3 pgrid(NB, 8);
    geps_prep_kernel<<<pgrid, 256>>>(codes, weight, A, Bm, bias, bctx);

    dim3 cgrid(LEN / LT, NB);
    geps_mma_kernel<<<cgrid, 256, SMEM_TOTAL>>>(input, out);
}

// round 13
// speedup vs baseline: 5.4575x; 1.1513x over previous
#include <cuda_runtime.h>
#include <cuda_fp16.h>
#include <cstdint>

#define NB   32
#define CIN  128
#define COUT 128
#define LEN  4096
#define KSZ  3
#define LT   128                // l-tile (M) per CTA
#define XSTRIDE 136             // fp16 per X row = 272B (ldsm-friendly)
#define STW 132                 // f32 staging row stride (words), 16B-aligned rows
#define WOFFB(buf) ((buf) * 16384)
#define STOFF 32768             // f32 staging tile [64][STW] (reused twice)
#define XOFF  66560             // X fp16 tile [130][XSTRIDE]
#define SMEM_TOTAL (XOFF + 130 * XSTRIDE * 2)    // 101920 bytes

// Prepped W images: [b][kk][ic] -> 64 i-rows x 128 o fp16 (swizzle at cp.async)
__device__ __align__(16) __half g_Wimg[NB * KSZ * 2 * 8192];   // 3.1 MB
__device__ float g_bias2[NB * COUT];

// ---------------------------------------------------------------------------
// helpers (baseline PTX, compiles for compute_103)
// ---------------------------------------------------------------------------
__device__ __forceinline__ uint32_t smem_u32(const void* p) {
    return (uint32_t)__cvta_generic_to_shared(p);
}
__device__ __forceinline__ void cp16(uint32_t saddr, const void* g) {
    asm volatile("cp.async.cg.shared.global [%0], [%1], 16;\n" :: "r"(saddr), "l"(g));
}
#define CP_COMMIT() asm volatile("cp.async.commit_group;\n" ::: "memory")
#define CP_WAIT0()  asm volatile("cp.async.wait_group 0;\n" ::: "memory")

__device__ __forceinline__ void ldsm4(uint32_t* d, uint32_t a) {
    asm volatile("ldmatrix.sync.aligned.m8n8.x4.shared.b16 {%0,%1,%2,%3}, [%4];"
                 : "=r"(d[0]), "=r"(d[1]), "=r"(d[2]), "=r"(d[3]) : "r"(a));
}
__device__ __forceinline__ void ldsm4t(uint32_t* d, uint32_t a) {
    asm volatile("ldmatrix.sync.aligned.m8n8.x4.trans.shared.b16 {%0,%1,%2,%3}, [%4];"
                 : "=r"(d[0]), "=r"(d[1]), "=r"(d[2]), "=r"(d[3]) : "r"(a));
}
__device__ __forceinline__ void mma16816(float* c, const uint32_t* a, const uint32_t* b) {
    asm volatile("mma.sync.aligned.m16n8k16.row.col.f32.f16.f16.f32 "
                 "{%0,%1,%2,%3}, {%4,%5,%6,%7}, {%8,%9}, {%0,%1,%2,%3};"
                 : "+f"(c[0]), "+f"(c[1]), "+f"(c[2]), "+f"(c[3])
                 : "r"(a[0]), "r"(a[1]), "r"(a[2]), "r"(a[3]), "r"(b[0]), "r"(b[1]));
}

// ---------------------------------------------------------------------------
// Kernel 1: hypernetwork weights -> fp16 W images, coalesced read + staged write.
// Block: (b, 16-o slab). Phase 1 reads weight contiguously (i in lane-low),
// stages through smem [kk][i][o_l] (stride 18); phase 2 writes coalesced u32.
// ---------------------------------------------------------------------------
__global__ void geps_prep_kernel(const float* __restrict__ codes,
                                 const float* __restrict__ weight,
                                 const float* __restrict__ A,
                                 const float* __restrict__ Bm,
                                 const float* __restrict__ bias,
                                 const float* __restrict__ bctx) {
    __shared__ __half s2[3 * 128 * 18];    // 13.5 KB
    const int b  = blockIdx.x;
    const int o0 = blockIdx.y * 16;
    const int tid = threadIdx.x;

    const float c00 = codes[b * 4 + 0];
    const float c01 = codes[b * 4 + 1];
    const float c10 = codes[b * 4 + 2];
    const float c11 = codes[b * 4 + 3];

#pragma unroll
    for (int r = 0; r < 8; ++r) {
        const int p  = r * 256 + tid;      // 2048 (o_l, i) pairs
        const int i  = p & 127;
        const int ol = p >> 7;
        const int o  = o0 + ol;
        const float* wp = weight + (size_t)(o * 128 + i) * 3;
        const float wk0 = wp[0], wk1 = wp[1], wk2 = wp[2];
#pragma unroll
        for (int kk = 0; kk < KSZ; ++kk) {
            const float a0 = A[i * 6 + kk];
            const float a1 = A[i * 6 + 3 + kk];
            const float g0 = a0 * c00 + a1 * c10;
            const float g1 = a0 * c01 + a1 * c11;
            const float wkk = (kk == 0) ? wk0 : (kk == 1 ? wk1 : wk2);
            const float cw = wkk + g0 * Bm[o * 6 + kk] + g1 * Bm[o * 6 + 3 + kk];
            s2[(kk * 128 + i) * 18 + ol] = __float2half(cw);
        }
    }
    __syncthreads();

#pragma unroll
    for (int r = 0; r < 12; ++r) {
        const int w  = r * 256 + tid;      // 3072 u32 (2 o each)
        const int o2 = w & 7;
        const int i  = (w >> 3) & 127;
        const int kk = w >> 10;
        const int ic = i >> 6, il = i & 63;
        const uint32_t v = *(const uint32_t*)&s2[(kk * 128 + i) * 18 + 2 * o2];
        ((uint32_t*)g_Wimg)[(size_t)((b * 3 + kk) * 2 + ic) * 4096
                            + il * 64 + (o0 >> 1) + o2] = v;
    }

    if (blockIdx.y == 0 && tid < COUT) {
        const int o = tid;
        g_bias2[b * COUT + o] = bias[o] + c00 * bctx[o] + c11 * bctx[COUT + o];
    }
}

// ---------------------------------------------------------------------------
// Kernel 2: HMMA fp16 implicit-GEMM conv. CTA 128l x 128o, 8 warps (2m x 4n),
// warp tile 64x32 (mt=4, nt=4) -> 1.5 ldsm-wf per MMA.
// ---------------------------------------------------------------------------
__global__ __launch_bounds__(256, 2)
void geps_mma_kernel(const float* __restrict__ x, float* __restrict__ out) {
    extern __shared__ char smem[];
    const int tid = threadIdx.x;
    const int wid = tid >> 5;
    const int lane = tid & 31;
    const int b  = blockIdx.y;
    const int l0 = blockIdx.x * LT;
    const float* xb = x + (size_t)b * CIN * LEN;

    float*  sT  = (float*)(smem + STOFF);            // staging [64][STW] f32
    float*  sC  = (float*)smem;                      // epilogue overlay [128][131]
    __half* sXh = (__half*)(smem + XOFF);            // [130][XSTRIDE] fp16
    const uint32_t sbase = smem_u32(smem);

    // ---- W chunk loader: 16KB, XOR-swizzled 16B chunks
    auto issue_w = [&](int step, int buf) {
        const int kk = step % 3, ic = step / 3;
        const __half* src = (const __half*)g_Wimg
                          + (size_t)((b * 3 + kk) * 2 + ic) * 8192;
        const uint32_t dbase = sbase + WOFFB(buf);
#pragma unroll
        for (int t = 0; t < 4; ++t) {
            const int v = tid + t * 256;
            const int row = v >> 4, c = v & 15;
            cp16(dbase + row * 256 + ((c ^ (row & 7)) << 4), src + v * 8);
        }
        CP_COMMIT();
    };

    issue_w(0, 0);    // overlap W0 with X fill

    // halo rows: row 0 = l0-1 (wrap), row 129 = l0+128 (wrap)
    {
        const int i = tid & 127;
        const int side = tid >> 7;
        const int gl = side ? ((l0 + LT) & (LEN - 1)) : ((l0 + LEN - 1) & (LEN - 1));
        const int row = side ? (LT + 1) : 0;
        sXh[row * XSTRIDE + i] = __float2half(xb[(size_t)i * LEN + gl]);
    }

    // ---- X fill in two i-halves through the f32 staging tile
#pragma unroll
    for (int ih = 0; ih < 2; ++ih) {
        const int i0h = 64 * ih;
        __syncthreads();      // sT free (prev half consumed / first entry)
        // stage A: coalesced LDG.128 -> conflict-free STS.128, sT[i][l]
#pragma unroll
        for (int r = 0; r < 8; ++r) {
            const int idx = r * 256 + tid;          // 2048 float4
            const int c = idx & 31;                 // l4-col 0..31
            const int i = idx >> 5;                 // 0..63
            const float4 v = *(const float4*)(xb + (size_t)(i0h + i) * LEN + l0 + 4 * c);
            *(float4*)(sT + i * STW + 4 * c) = v;
        }
        __syncthreads();
        // stage B: transpose, conflict-free LDS.32, write sXh[l+1][i] as u64
        {
            const int rB  = tid & 127;              // l 0..127
            const int ibB = tid >> 7;               // 0..1
#pragma unroll
            for (int t = 0; t < 8; ++t) {
                const int ib = ibB + 2 * t;         // 0..15 -> i_local 4*ib..+3
                const float a0 = sT[(4 * ib + 0) * STW + rB];
                const float a1 = sT[(4 * ib + 1) * STW + rB];
                const float a2 = sT[(4 * ib + 2) * STW + rB];
                const float a3 = sT[(4 * ib + 3) * STW + rB];
                union { uint2 u; __half2 h[2]; } pk;
                pk.h[0] = __floats2half2_rn(a0, a1);
                pk.h[1] = __floats2half2_rn(a2, a3);
                *(uint2*)(&sXh[(rB + 1) * XSTRIDE + i0h + 4 * ib]) = pk.u;
            }
        }
    }

    // ---- lane-derived ldmatrix address components
    const int g = lane >> 3, r = lane & 7;
    const int arow = ((g & 1) << 3) + r;
    const int achk = g >> 1;
    const int wm = wid & 1, wn = wid >> 1;
    const int m0 = 64 * wm, n0 = 32 * wn;

    float acc[4][4][4];
#pragma unroll
    for (int mt = 0; mt < 4; ++mt)
#pragma unroll
        for (int nt = 0; nt < 4; ++nt)
#pragma unroll
            for (int q = 0; q < 4; ++q) acc[mt][nt][q] = 0.f;

    const uint32_t xhib = sbase + XOFF;

    for (int step = 0; step < 6; ++step) {
        const int buf = step & 1;
        CP_WAIT0();
        __syncthreads();                 // W(step) + X visible
        if (step + 1 < 6) issue_w(step + 1, buf ^ 1);

        const int kk = step % 3;
        const int ic = step / 3;
        const uint32_t wb_ = sbase + WOFFB(buf);

#pragma unroll
        for (int ks = 0; ks < 4; ++ks) {
            uint32_t ah[4][4], bw[8];
#pragma unroll
            for (int mt = 0; mt < 4; ++mt) {
                const uint32_t off =
                    (uint32_t)((kk + m0 + 16 * mt + arow) * 272 +
                               (8 * ic + 2 * ks + achk) * 16);
                ldsm4(ah[mt], xhib + off);
            }
            const int rowB = 16 * ks + arow;
#pragma unroll
            for (int h = 0; h < 2; ++h) {
                const int cB = 4 * wn + 2 * h + achk;
                const uint32_t off =
                    (uint32_t)(rowB * 256 + ((cB ^ (rowB & 7)) << 4));
                ldsm4t(&bw[4 * h], wb_ + off);
            }
#pragma unroll
            for (int mt = 0; mt < 4; ++mt)
#pragma unroll
                for (int nt = 0; nt < 4; ++nt)
                    mma16816(acc[mt][nt], ah[mt], &bw[2 * nt]);
        }
    }

    // ---- epilogue: stage C[l][o] through smem (stride 131), coalesced stores
    __syncthreads();
    {
        const int gr = lane >> 2, cid = lane & 3;
#pragma unroll
        for (int mt = 0; mt < 4; ++mt)
#pragma unroll
            for (int nt = 0; nt < 4; ++nt) {
                const int m = m0 + 16 * mt + gr;
                const int n = n0 + 8 * nt + 2 * cid;
                sC[m * 131 + n]           = acc[mt][nt][0];
                sC[m * 131 + n + 1]       = acc[mt][nt][1];
                sC[(m + 8) * 131 + n]     = acc[mt][nt][2];
                sC[(m + 8) * 131 + n + 1] = acc[mt][nt][3];
            }
    }
    __syncthreads();
    {
        const float* bb = g_bias2 + b * COUT;
#pragma unroll
        for (int jj = 0; jj < 16; ++jj) {
            const int o = wid * 16 + jj;
            const float bv = bb[o];
            float* op = out + ((size_t)b * COUT + o) * LEN + l0;
#pragma unroll
            for (int qh = 0; qh < 4; ++qh) {
                const int l = 32 * qh + lane;
                op[l] = sC[l * 131 + o] + bv;
            }
        }
    }
}

extern "C" void kernel_launch(void* const* d_in, const int* in_sizes, int n_in,
                              void* d_out, int out_size) {
    const float* input  = (const float*)d_in[0];   // (32,128,4096)
    const float* codes  = (const float*)d_in[1];   // (32,2,2)
    const float* weight = (const float*)d_in[2];   // (128,128,3)
    const float* A      = (const float*)d_in[3];   // (128,2,3)
    const float* Bm     = (const float*)d_in[4];   // (128,2,3)
    const float* bias   = (const float*)d_in[5];   // (128,)
    const float* bctx   = (const float*)d_in[6];   // (2,128)
    float* out = (float*)d_out;                    // (32,128,4096)

    cudaFuncSetAttribute(geps_mma_kernel,
                         cudaFuncAttributeMaxDynamicSharedMemorySize, SMEM_TOTAL);

    dim3 pgrid(NB, 8);
    geps_prep_kernel<<<pgrid, 256>>>(codes, weight, A, Bm, bias, bctx);

    dim3 cgrid(LEN / LT, NB);
    geps_mma_kernel<<<cgrid, 256, SMEM_TOTAL>>>(input, out);
}